// round 14
// baseline (speedup 1.0000x reference)
#include <cuda_runtime.h>

// SimSiamLoss: n=8192, d=128, n_classes=512
// loss = -0.5 * [ sum_c Psum[c]·Zsum[c] - sum_i pn_i·zn_i ] / npairs
// where Psum/Zsum are per-class sums of L2-normalized rows,
// npairs = sum_c count_c*(count_c-1)/2 (clamped to >= 1).
//
// targets dtype: reference says int64, but JAX default config coerces to
// int32. We detect at runtime: for an int64 (LE) buffer all odd 32-bit words
// are zero (values in [0,512)); for int32 data they are real targets.

#define N_ROWS  8192
#define DIM     128
#define NCLS    512

__device__ __align__(16) float g_psum[NCLS * DIM];
__device__ __align__(16) float g_zsum[NCLS * DIM];
__device__ float g_diag_arr[N_ROWS];
__device__ int   g_count[NCLS];
__device__ int   g_is64;

// Blocks 0..255: zero accumulators. Block 256: dtype detection.
__global__ void __launch_bounds__(256) zero_detect_kernel(const int* __restrict__ t32) {
    if (blockIdx.x < 256) {
        int i = blockIdx.x * 256 + threadIdx.x;   // covers NCLS*DIM = 65536
        g_psum[i] = 0.0f;
        g_zsum[i] = 0.0f;
        if (i < NCLS) g_count[i] = 0;
    } else {
        __shared__ int any;
        if (threadIdx.x == 0) any = 0;
        __syncthreads();
        int local = 0;
        // Odd words 2i+1 for i<4096 stay within 8192 ints (valid either dtype).
        for (int i = threadIdx.x; i < 4096; i += 256)
            local |= t32[2 * i + 1];
        if (local) atomicOr(&any, 1);
        __syncthreads();
        if (threadIdx.x == 0) g_is64 = (any == 0) ? 1 : 0;
    }
}

// One WARP per row: float4 loads, shfl reductions, scalar red.global scatter.
__global__ void __launch_bounds__(256) row_kernel(
    const float* __restrict__ ps,
    const float* __restrict__ zs,
    const int* __restrict__ t32)
{
    const int warp_in_blk = threadIdx.x >> 5;
    const int l           = threadIdx.x & 31;
    const int row         = blockIdx.x * 8 + warp_in_blk;

    const float4 p = ((const float4*)ps)[row * 32 + l];
    const float4 z = ((const float4*)zs)[row * 32 + l];

    float pp = p.x * p.x + p.y * p.y + p.z * p.z + p.w * p.w;
    float zz = z.x * z.x + z.y * z.y + z.z * z.z + z.w * z.w;
    #pragma unroll
    for (int o = 16; o; o >>= 1) {
        pp += __shfl_xor_sync(0xffffffffu, pp, o);
        zz += __shfl_xor_sync(0xffffffffu, zz, o);
    }

    const float pinv = 1.0f / fmaxf(sqrtf(pp), 1e-8f);
    const float zinv = 1.0f / fmaxf(sqrtf(zz), 1e-8f);

    float4 pn, zn;
    pn.x = p.x * pinv; pn.y = p.y * pinv; pn.z = p.z * pinv; pn.w = p.w * pinv;
    zn.x = z.x * zinv; zn.y = z.y * zinv; zn.z = z.z * zinv; zn.w = z.w * zinv;

    int c = g_is64 ? t32[2 * row] : t32[row];   // low word if int64
    c = min(max(c, 0), NCLS - 1);               // trap insurance

    float* pdst = &g_psum[c * DIM + l * 4];
    float* zdst = &g_zsum[c * DIM + l * 4];
    atomicAdd(pdst + 0, pn.x);
    atomicAdd(pdst + 1, pn.y);
    atomicAdd(pdst + 2, pn.z);
    atomicAdd(pdst + 3, pn.w);
    atomicAdd(zdst + 0, zn.x);
    atomicAdd(zdst + 1, zn.y);
    atomicAdd(zdst + 2, zn.z);
    atomicAdd(zdst + 3, zn.w);

    // per-row diagonal term pn·zn -> plain store (no contended atomic)
    float dg = pn.x * zn.x + pn.y * zn.y + pn.z * zn.z + pn.w * zn.w;
    #pragma unroll
    for (int o = 16; o; o >>= 1)
        dg += __shfl_xor_sync(0xffffffffu, dg, o);

    if (l == 0) {
        g_diag_arr[row] = dg;
        atomicAdd(&g_count[c], 1);
    }
}

__global__ void __launch_bounds__(256) finalize_kernel(float* __restrict__ out)
{
    const int t = threadIdx.x;
    const int w = t >> 5;
    const int l = t & 31;

    float acc = 0.0f;
    for (int i = t; i < NCLS * DIM; i += 256)
        acc += g_psum[i] * g_zsum[i];

    float dg = 0.0f;
    for (int i = t; i < N_ROWS; i += 256)
        dg += g_diag_arr[i];

    float np = 0.0f;
    for (int c = t; c < NCLS; c += 256) {
        float cnt = (float)g_count[c];
        np += 0.5f * cnt * (cnt - 1.0f);
    }

    __shared__ float sa[8], sd[8], sn[8];
    #pragma unroll
    for (int o = 16; o; o >>= 1) {
        acc += __shfl_xor_sync(0xffffffffu, acc, o);
        dg  += __shfl_xor_sync(0xffffffffu, dg, o);
        np  += __shfl_xor_sync(0xffffffffu, np, o);
    }
    if (l == 0) { sa[w] = acc; sd[w] = dg; sn[w] = np; }
    __syncthreads();

    if (t == 0) {
        float A = 0.0f, D = 0.0f, NP = 0.0f;
        #pragma unroll
        for (int i = 0; i < 8; i++) { A += sa[i]; D += sd[i]; NP += sn[i]; }
        const float total = A - D;        // ordered same-class pairs, i != j
        NP = fmaxf(NP, 1.0f);
        out[0] = -0.5f * total / NP;
    }
}

extern "C" void kernel_launch(void* const* d_in, const int* in_sizes, int n_in,
                              void* d_out, int out_size)
{
    const float* ps  = (const float*)d_in[0];
    const float* zs  = (const float*)d_in[1];
    const int*   t32 = (const int*)d_in[2];
    float*       out = (float*)d_out;

    zero_detect_kernel<<<257, 256>>>(t32);
    row_kernel<<<N_ROWS / 8, 256>>>(ps, zs, t32);
    finalize_kernel<<<1, 256>>>(out);
}

// round 17
// speedup vs baseline: 1.1577x; 1.1577x over previous
#include <cuda_runtime.h>

// SimSiamLoss fused single-kernel version.
// loss = -0.5 * [ sum_c Psum[c]·Zsum[c] - sum_i pn_i·zn_i ] / npairs
// Confirmed R14: targets arrive as int32 (JAX x64-disabled); detection kept
// for robustness. Single-wave grid (148 blocks <= SM count) + software grid
// barrier fuses zero/detect, row scatter, and finalize into one launch.

#define N_ROWS  8192
#define DIM     128
#define NCLS    512
#define NBLK    148
#define NTHR    256
#define TOTTHR  (NBLK * NTHR)     // 37888
#define NWARPS  (TOTTHR / 32)     // 1184

__device__ __align__(16) float g_psum[NCLS * DIM];
__device__ __align__(16) float g_zsum[NCLS * DIM];
__device__ int   g_count[NCLS];
__device__ int   g_is64;
__device__ float g_res[3];        // [0]=dot(psum,zsum) [1]=npairs [2]=diag
__device__ unsigned int g_bar_count;
__device__ unsigned int g_bar_gen;

__device__ __forceinline__ void grid_barrier() {
    __syncthreads();
    if (threadIdx.x == 0) {
        unsigned int gen = atomicAdd(&g_bar_gen, 0u);   // read current phase
        __threadfence();                                // publish prior writes
        unsigned int t = atomicAdd(&g_bar_count, 1u);
        if (t == NBLK - 1) {
            g_bar_count = 0;                            // all arrived; reset
            __threadfence();
            atomicAdd(&g_bar_gen, 1u);                  // release
        } else {
            while (atomicAdd(&g_bar_gen, 0u) == gen) { __nanosleep(64); }
        }
    }
    __syncthreads();
}

__global__ void __launch_bounds__(NTHR) fused_kernel(
    const float* __restrict__ ps,
    const float* __restrict__ zs,
    const int*   __restrict__ t32,
    float*       __restrict__ out)
{
    const int tid  = threadIdx.x;
    const int gtid = blockIdx.x * NTHR + tid;
    const int l    = tid & 31;
    const int wblk = tid >> 5;                    // warp in block (0..7)
    const int gw   = blockIdx.x * 8 + wblk;       // global warp id

    // ---------------- Phase 0: zero accumulators (+ dtype detect, block 0)
    for (int i = gtid; i < NCLS * DIM; i += TOTTHR) {
        g_psum[i] = 0.0f;
        g_zsum[i] = 0.0f;
        if (i < NCLS) g_count[i] = 0;
    }
    if (gtid < 3) g_res[gtid] = 0.0f;

    if (blockIdx.x == 0) {
        __shared__ int any;
        if (tid == 0) any = 0;
        __syncthreads();
        int local = 0;
        // Odd 32-bit words: all-zero iff buffer is int64 LE with values <512.
        for (int i = tid; i < 4096; i += NTHR)
            local |= t32[2 * i + 1];
        if (local) atomicOr(&any, 1);
        __syncthreads();
        if (tid == 0) g_is64 = (any == 0) ? 1 : 0;
    }

    grid_barrier();   // A: zeroing + g_is64 visible everywhere

    // ---------------- Phase 1: rows (warp per row, strided)
    const int is64 = g_is64;
    float dg_lane = 0.0f;                         // per-lane diag partial
    for (int row = gw; row < N_ROWS; row += NWARPS) {
        const float4 p = ((const float4*)ps)[row * 32 + l];
        const float4 z = ((const float4*)zs)[row * 32 + l];

        float pp = p.x * p.x + p.y * p.y + p.z * p.z + p.w * p.w;
        float zz = z.x * z.x + z.y * z.y + z.z * z.z + z.w * z.w;
        #pragma unroll
        for (int o = 16; o; o >>= 1) {
            pp += __shfl_xor_sync(0xffffffffu, pp, o);
            zz += __shfl_xor_sync(0xffffffffu, zz, o);
        }
        const float pinv = 1.0f / fmaxf(sqrtf(pp), 1e-8f);
        const float zinv = 1.0f / fmaxf(sqrtf(zz), 1e-8f);

        float4 pn, zn;
        pn.x = p.x * pinv; pn.y = p.y * pinv; pn.z = p.z * pinv; pn.w = p.w * pinv;
        zn.x = z.x * zinv; zn.y = z.y * zinv; zn.z = z.z * zinv; zn.w = z.w * zinv;

        int c = is64 ? t32[2 * row] : t32[row];
        c = min(max(c, 0), NCLS - 1);             // trap insurance

        float* pdst = &g_psum[c * DIM + l * 4];
        float* zdst = &g_zsum[c * DIM + l * 4];
        atomicAdd(pdst + 0, pn.x);
        atomicAdd(pdst + 1, pn.y);
        atomicAdd(pdst + 2, pn.z);
        atomicAdd(pdst + 3, pn.w);
        atomicAdd(zdst + 0, zn.x);
        atomicAdd(zdst + 1, zn.y);
        atomicAdd(zdst + 2, zn.z);
        atomicAdd(zdst + 3, zn.w);

        dg_lane += pn.x * zn.x + pn.y * zn.y + pn.z * zn.z + pn.w * zn.w;

        if (l == 0) atomicAdd(&g_count[c], 1);
    }
    // one warp-reduce + one atomic per warp for the diagonal
    #pragma unroll
    for (int o = 16; o; o >>= 1)
        dg_lane += __shfl_xor_sync(0xffffffffu, dg_lane, o);
    if (l == 0) atomicAdd(&g_res[2], dg_lane);

    grid_barrier();   // B: scatter + counts complete

    // ---------------- Phase 2: dot(psum, zsum) + npairs partials
    float acc = 0.0f;
    for (int i = gtid; i < NCLS * DIM; i += TOTTHR)
        acc += g_psum[i] * g_zsum[i];

    float np = 0.0f;
    if (gtid < NCLS) {
        float cnt = (float)g_count[gtid];
        np = 0.5f * cnt * (cnt - 1.0f);
    }

    __shared__ float sa[8], sn[8];
    #pragma unroll
    for (int o = 16; o; o >>= 1) {
        acc += __shfl_xor_sync(0xffffffffu, acc, o);
        np  += __shfl_xor_sync(0xffffffffu, np, o);
    }
    if (l == 0) { sa[wblk] = acc; sn[wblk] = np; }
    __syncthreads();
    if (tid == 0) {
        float A = 0.0f, NP = 0.0f;
        #pragma unroll
        for (int i = 0; i < 8; i++) { A += sa[i]; NP += sn[i]; }
        atomicAdd(&g_res[0], A);
        atomicAdd(&g_res[1], NP);
    }

    grid_barrier();   // C: partials complete

    if (blockIdx.x == 0 && tid == 0) {
        const float total = g_res[0] - g_res[2];  // ordered same-class pairs, i != j
        const float NP    = fmaxf(g_res[1], 1.0f);
        out[0] = -0.5f * total / NP;
    }
}

extern "C" void kernel_launch(void* const* d_in, const int* in_sizes, int n_in,
                              void* d_out, int out_size)
{
    const float* ps  = (const float*)d_in[0];
    const float* zs  = (const float*)d_in[1];
    const int*   t32 = (const int*)d_in[2];
    float*       out = (float*)d_out;

    fused_kernel<<<NBLK, NTHR>>>(ps, zs, t32, out);
}